// round 1
// baseline (speedup 1.0000x reference)
#include <cuda_runtime.h>

#define T_DIM 8192
#define H_DIM 32
#define N_DIM 64
#define TB 8                 // timesteps per staged batch
#define NB (T_DIM / TB)      // 1024 batches
#define JB 16                // j-columns per block
#define IC 8                 // i's per thread (4 packed pairs)
#define NG 8                 // i-groups per block (NG*IC = 64)
#define THREADS 128          // NG * JB / ... = 8 groups x 16 j

typedef unsigned long long ull;

__device__ __forceinline__ ull pk2(float x, float y) {
    ull r; asm("mov.b64 %0, {%1,%2};" : "=l"(r) : "f"(x), "f"(y)); return r;
}
__device__ __forceinline__ void upk2(float& x, float& y, ull a) {
    asm("mov.b64 {%0,%1}, %2;" : "=f"(x), "=f"(y) : "l"(a));
}
__device__ __forceinline__ ull fma2(ull a, ull b, ull c) {
    ull d; asm("fma.rn.f32x2 %0, %1, %2, %3;" : "=l"(d) : "l"(a), "l"(b), "l"(c)); return d;
}
__device__ __forceinline__ ull mul2(ull a, ull b) {
    ull d; asm("mul.rn.f32x2 %0, %1, %2;" : "=l"(d) : "l"(a), "l"(b)); return d;
}
__device__ __forceinline__ ull add2(ull a, ull b) {
    ull d; asm("add.rn.f32x2 %0, %1, %2;" : "=l"(d) : "l"(a), "l"(b)); return d;
}

// Prepass scratch: rtfk_sum[t][h] = sum_i r*tf*k  (1 MB static)
__device__ float g_rtfk[T_DIM * H_DIM];

// ---------------- Prepass: bonus scalar per (t,h) ----------------
__global__ void rtfk_kernel(const float* __restrict__ k,
                            const float* __restrict__ r,
                            const float* __restrict__ tf) {
    int gw = (blockIdx.x * blockDim.x + threadIdx.x) >> 5;  // warp id = (t*H + h)
    int lane = threadIdx.x & 31;
    if (gw >= T_DIM * H_DIM) return;
    int h = gw % H_DIM;
    const float2 kk = *(const float2*)(k + (size_t)gw * N_DIM + 2 * lane);
    const float2 rr = *(const float2*)(r + (size_t)gw * N_DIM + 2 * lane);
    const float2 tt = *(const float2*)(tf + (size_t)h * N_DIM + 2 * lane);
    float s = kk.x * rr.x * tt.x + kk.y * rr.y * tt.y;
#pragma unroll
    for (int o = 16; o > 0; o >>= 1) s += __shfl_xor_sync(0xffffffffu, s, o);
    if (lane == 0) g_rtfk[gw] = s;
}

// ---------------- Main WKV recurrence ----------------
// grid: (N_DIM/JB, H_DIM) = (4, 32), 128 threads.
// thread (cg, cj): i in [cg*8, cg*8+8), j = blockIdx.x*16 + cj.
__global__ __launch_bounds__(THREADS, 1)
void wkv_kernel(const float* __restrict__ k, const float* __restrict__ v,
                const float* __restrict__ r, const float* __restrict__ s0,
                const float* __restrict__ td, float* __restrict__ out,
                int out_size) {
    __shared__ float sk[3][TB][N_DIM];
    __shared__ float sr[3][TB][N_DIM];
    __shared__ float sw[3][TB][N_DIM];
    __shared__ float sv[3][TB][JB];
    __shared__ float sb[3][TB];
    __shared__ ull   part[2][TB][JB][NG + 1];   // +1 pad against bank conflicts

    const int tid = threadIdx.x;
    const int h   = blockIdx.y;
    const int j0  = blockIdx.x * JB;
    const int cg  = tid >> 4;        // 0..7 (i-group, also tl for reduction)
    const int cj  = tid & 15;        // 0..15
    const int i0  = cg * IC;
    const int j   = j0 + cj;

    // ---- load initial state: 4 packed (i, i+1) pairs for column j ----
    ull S[4];
#pragma unroll
    for (int p = 0; p < 4; ++p) {
        int i = i0 + 2 * p;
        float a = s0[((size_t)h * N_DIM + i) * N_DIM + j];
        float b = s0[((size_t)h * N_DIM + i + 1) * N_DIM + j];
        S[p] = pk2(a, b);
    }

    const int srow = tid >> 4;            // 0..7  (row in batch)
    const int sc4  = (tid & 15) << 2;     // 0,4,...,60

    auto stage = [&](int bb, int slot) {
        int t0 = bb * TB;
        size_t base = ((size_t)(t0 + srow) * H_DIM + h) * N_DIM;
        *(float4*)&sk[slot][srow][sc4] = *(const float4*)(k  + base + sc4);
        *(float4*)&sr[slot][srow][sc4] = *(const float4*)(r  + base + sc4);
        *(float4*)&sw[slot][srow][sc4] = *(const float4*)(td + base + sc4);
        if (tid < 32) {
            int vr = tid >> 2, vc = (tid & 3) << 2;
            size_t vb = ((size_t)(t0 + vr) * H_DIM + h) * N_DIM + j0 + vc;
            *(float4*)&sv[slot][vr][vc] = *(const float4*)(v + vb);
        }
        if (tid < TB) sb[slot][tid] = g_rtfk[(size_t)(t0 + tid) * H_DIM + h];
    };

    stage(0, 0);
    stage(1, 1);
    __syncthreads();

    for (int b = 0; b < NB; ++b) {
        const int slot = b % 3;
        if (b + 2 < NB) stage(b + 2, (b + 2) % 3);   // prefetch 2 batches ahead
        const int pb = b & 1;

        ull pout[TB];
#pragma unroll
        for (int tl = 0; tl < TB; ++tl) {
            ulonglong2 kA = *(const ulonglong2*)&sk[slot][tl][i0];
            ulonglong2 kB = *(const ulonglong2*)&sk[slot][tl][i0 + 4];
            ulonglong2 rA = *(const ulonglong2*)&sr[slot][tl][i0];
            ulonglong2 rB = *(const ulonglong2*)&sr[slot][tl][i0 + 4];
            ulonglong2 wA = *(const ulonglong2*)&sw[slot][tl][i0];
            ulonglong2 wB = *(const ulonglong2*)&sw[slot][tl][i0 + 4];
            float vs = sv[slot][tl][cj];
            ull v2 = pk2(vs, vs);
            ull p = 0ULL;
#define PAIR(KP, RP, WP, SR_) do { \
            ull kv_ = mul2((KP), v2); \
            p = fma2((RP), (SR_), p); \
            (SR_) = fma2((WP), (SR_), kv_); } while (0)
            PAIR(kA.x, rA.x, wA.x, S[0]);
            PAIR(kA.y, rA.y, wA.y, S[1]);
            PAIR(kB.x, rB.x, wB.x, S[2]);
            PAIR(kB.y, rB.y, wB.y, S[3]);
#undef PAIR
            pout[tl] = p;
        }

        // capture values needed after the barrier (slot may be restaged next iter)
        float myv = sv[slot][cg][cj];
        float myb = sb[slot][cg];

#pragma unroll
        for (int tl = 0; tl < TB; ++tl)
            part[pb][tl][cj][cg] = pout[tl];

        __syncthreads();

        // reduce over the 8 i-groups: this thread owns (t = b*TB + cg, j)
        const ull* pp = part[pb][cg][cj];
        ull s01 = add2(pp[0], pp[1]);
        ull s23 = add2(pp[2], pp[3]);
        ull s45 = add2(pp[4], pp[5]);
        ull s67 = add2(pp[6], pp[7]);
        ull st  = add2(add2(s01, s23), add2(s45, s67));
        float x, y; upk2(x, y, st);
        float o = fmaf(myb, myv, x + y);
        int t = b * TB + cg;
        out[((size_t)t * H_DIM + h) * N_DIM + j] = o;
    }

    // ---- final state ----
    size_t so = (size_t)T_DIM * H_DIM * N_DIM;
    if ((size_t)out_size >= so + (size_t)H_DIM * N_DIM * N_DIM) {
#pragma unroll
        for (int p = 0; p < 4; ++p) {
            float a, b;
            upk2(a, b, S[p]);
            int i = i0 + 2 * p;
            out[so + ((size_t)h * N_DIM + i) * N_DIM + j]     = a;
            out[so + ((size_t)h * N_DIM + i + 1) * N_DIM + j] = b;
        }
    }
}

extern "C" void kernel_launch(void* const* d_in, const int* in_sizes, int n_in,
                              void* d_out, int out_size) {
    const float* k  = (const float*)d_in[0];
    const float* v  = (const float*)d_in[1];
    const float* r  = (const float*)d_in[2];
    const float* s0 = (const float*)d_in[3];
    const float* tf = (const float*)d_in[4];
    const float* td = (const float*)d_in[5];
    float* out = (float*)d_out;

    // Prepass: one warp per (t,h) — 262144 warps
    int warps = T_DIM * H_DIM;
    int blocks = (warps * 32) / 256;
    rtfk_kernel<<<blocks, 256>>>(k, r, tf);

    dim3 grid(N_DIM / JB, H_DIM);   // (4, 32)
    wkv_kernel<<<grid, THREADS>>>(k, v, r, s0, td, out, out_size);
}

// round 2
// speedup vs baseline: 1.1564x; 1.1564x over previous
#include <cuda_runtime.h>

#define T_DIM 8192
#define H_DIM 32
#define N_DIM 64
#define TB 8                 // timesteps per staged batch
#define NB (T_DIM / TB)      // 1024 batches
#define JB 16                // j-columns per block
#define IC 8                 // i's per thread (4 packed pairs)
#define NG 8                 // i-groups per block
#define THREADS 128
#define RING 6               // cp.async ring slots (issue distance 5)

typedef unsigned long long ull;

__device__ __forceinline__ ull pk2(float x, float y) {
    ull r; asm("mov.b64 %0, {%1,%2};" : "=l"(r) : "f"(x), "f"(y)); return r;
}
__device__ __forceinline__ void upk2(float& x, float& y, ull a) {
    asm("mov.b64 {%0,%1}, %2;" : "=f"(x), "=f"(y) : "l"(a));
}
__device__ __forceinline__ ull fma2(ull a, ull b, ull c) {
    ull d; asm("fma.rn.f32x2 %0, %1, %2, %3;" : "=l"(d) : "l"(a), "l"(b), "l"(c)); return d;
}
__device__ __forceinline__ ull mul2(ull a, ull b) {
    ull d; asm("mul.rn.f32x2 %0, %1, %2;" : "=l"(d) : "l"(a), "l"(b)); return d;
}

__device__ __forceinline__ void cp16(void* s, const void* g) {
    unsigned sa = (unsigned)__cvta_generic_to_shared(s);
    asm volatile("cp.async.cg.shared.global [%0], [%1], 16;" :: "r"(sa), "l"(g) : "memory");
}
#define CP_COMMIT() asm volatile("cp.async.commit_group;" ::: "memory")
#define CP_WAIT(n)  asm volatile("cp.async.wait_group %0;" :: "n"(n) : "memory")

// Prepass scratch: rtfk[t][h] = sum_i r*tf*k
__device__ float g_rtfk[T_DIM * H_DIM];

// ---------------- Prepass: bonus scalar per (t,h) ----------------
__global__ void rtfk_kernel(const float* __restrict__ k,
                            const float* __restrict__ r,
                            const float* __restrict__ tf) {
    int gw = (blockIdx.x * blockDim.x + threadIdx.x) >> 5;  // warp id = (t*H + h)
    int lane = threadIdx.x & 31;
    if (gw >= T_DIM * H_DIM) return;
    int h = gw % H_DIM;
    const float2 kk = *(const float2*)(k + (size_t)gw * N_DIM + 2 * lane);
    const float2 rr = *(const float2*)(r + (size_t)gw * N_DIM + 2 * lane);
    const float2 tt = *(const float2*)(tf + (size_t)h * N_DIM + 2 * lane);
    float s = kk.x * rr.x * tt.x + kk.y * rr.y * tt.y;
#pragma unroll
    for (int o = 16; o > 0; o >>= 1) s += __shfl_xor_sync(0xffffffffu, s, o);
    if (lane == 0) g_rtfk[gw] = s;
}

// ---------------- Main WKV recurrence ----------------
// grid: (N_DIM/JB, H_DIM) = (4, 32), 128 threads.
// thread (cg, cj): i in [cg*8, cg*8+8), j = blockIdx.x*16 + cj.
__global__ __launch_bounds__(THREADS, 1)
void wkv_kernel(const float* __restrict__ k, const float* __restrict__ v,
                const float* __restrict__ r, const float* __restrict__ s0,
                const float* __restrict__ td, float* __restrict__ out,
                int out_size) {
    __shared__ __align__(16) float sk[RING][TB][N_DIM];
    __shared__ __align__(16) float sr[RING][TB][N_DIM];
    __shared__ __align__(16) float sw[RING][TB][N_DIM];
    __shared__ __align__(16) float sv[RING][TB][JB];
    __shared__ float part[2][TB][NG][JB];   // [tl][cg][cj] -> conflict-free STS

    const int tid = threadIdx.x;
    const int h   = blockIdx.y;
    const int j0  = blockIdx.x * JB;
    const int cg  = tid >> 4;        // 0..7 (i-group; also the tl this thread reduces)
    const int cj  = tid & 15;        // 0..15
    const int i0  = cg * IC;
    const int j   = j0 + cj;

    // ---- initial state: 4 packed (i, i+1) pairs for column j ----
    ull S[4];
#pragma unroll
    for (int p = 0; p < 4; ++p) {
        int i = i0 + 2 * p;
        float a = s0[((size_t)h * N_DIM + i) * N_DIM + j];
        float b = s0[((size_t)h * N_DIM + i + 1) * N_DIM + j];
        S[p] = pk2(a, b);
    }

    const int srow = tid >> 4;            // 0..7  (row in batch)
    const int sc4  = (tid & 15) << 2;     // 0,4,...,60

    auto stage = [&](int bb, int slot) {
        int t0 = bb * TB;
        size_t base = ((size_t)(t0 + srow) * H_DIM + h) * N_DIM + sc4;
        cp16(&sk[slot][srow][sc4], k  + base);
        cp16(&sr[slot][srow][sc4], r  + base);
        cp16(&sw[slot][srow][sc4], td + base);
        if (tid < 32) {
            int vr = tid >> 2, vc = (tid & 3) << 2;
            cp16(&sv[slot][vr][vc],
                 v + ((size_t)(t0 + vr) * H_DIM + h) * N_DIM + j0 + vc);
        }
        CP_COMMIT();
    };

    // prologue: fill 5 of 6 ring slots
#pragma unroll
    for (int d = 0; d < 5; ++d) stage(d, d);

    float vprev = 0.f, bprev = 0.f;

    for (int b = 0; b < NB; ++b) {
        const int slot = b % RING;
        CP_WAIT(4);            // batch b's group is complete
        __syncthreads();       // data visible; all warps past iter b-1 reads

        if (b + 5 < NB) stage(b + 5, (b + 5) % RING);

        // bonus for batch b (used at iter b+1) — pipelined LDG
        float bcur = g_rtfk[(size_t)(b * TB + cg) * H_DIM + h];

        // ---- reduce batch b-1 partials (stored last iter), write out ----
        if (b > 0) {
            const float* pp = &part[(b - 1) & 1][cg][0][cj];
            float s = ((pp[0] + pp[JB]) + (pp[2 * JB] + pp[3 * JB]))
                    + ((pp[4 * JB] + pp[5 * JB]) + (pp[6 * JB] + pp[7 * JB]));
            float o = fmaf(bprev, vprev, s);
            int t = (b - 1) * TB + cg;
            out[((size_t)t * H_DIM + h) * N_DIM + j] = o;
        }

        // ---- compute batch b ----
        float ps[TB];
#pragma unroll
        for (int tl = 0; tl < TB; ++tl) {
            ulonglong2 kA = *(const ulonglong2*)&sk[slot][tl][i0];
            ulonglong2 kB = *(const ulonglong2*)&sk[slot][tl][i0 + 4];
            ulonglong2 rA = *(const ulonglong2*)&sr[slot][tl][i0];
            ulonglong2 rB = *(const ulonglong2*)&sr[slot][tl][i0 + 4];
            ulonglong2 wA = *(const ulonglong2*)&sw[slot][tl][i0];
            ulonglong2 wB = *(const ulonglong2*)&sw[slot][tl][i0 + 4];
            float vs = sv[slot][tl][cj];
            ull v2 = pk2(vs, vs);
            ull p = 0ULL;
#define PAIR(KP, RP, WP, SR_) do { \
            ull kv_ = mul2((KP), v2); \
            p = fma2((RP), (SR_), p); \
            (SR_) = fma2((WP), (SR_), kv_); } while (0)
            PAIR(kA.x, rA.x, wA.x, S[0]);
            PAIR(kA.y, rA.y, wA.y, S[1]);
            PAIR(kB.x, rB.x, wB.x, S[2]);
            PAIR(kB.y, rB.y, wB.y, S[3]);
#undef PAIR
            float x, y; upk2(x, y, p);
            ps[tl] = x + y;
        }

        // v for batch b at (t-local = cg, j) — needed at iter b+1 reduce
        float vcur = sv[slot][cg][cj];

#pragma unroll
        for (int tl = 0; tl < TB; ++tl)
            part[b & 1][tl][cg][cj] = ps[tl];

        vprev = vcur;
        bprev = bcur;
    }

    // ---- epilogue: reduce final batch ----
    __syncthreads();
    {
        const float* pp = &part[(NB - 1) & 1][cg][0][cj];
        float s = ((pp[0] + pp[JB]) + (pp[2 * JB] + pp[3 * JB]))
                + ((pp[4 * JB] + pp[5 * JB]) + (pp[6 * JB] + pp[7 * JB]));
        float o = fmaf(bprev, vprev, s);
        int t = (NB - 1) * TB + cg;
        out[((size_t)t * H_DIM + h) * N_DIM + j] = o;
    }

    // ---- final state ----
    size_t so = (size_t)T_DIM * H_DIM * N_DIM;
    if ((size_t)out_size >= so + (size_t)H_DIM * N_DIM * N_DIM) {
#pragma unroll
        for (int p = 0; p < 4; ++p) {
            float a, b;
            upk2(a, b, S[p]);
            int i = i0 + 2 * p;
            out[so + ((size_t)h * N_DIM + i) * N_DIM + j]     = a;
            out[so + ((size_t)h * N_DIM + i + 1) * N_DIM + j] = b;
        }
    }
}

extern "C" void kernel_launch(void* const* d_in, const int* in_sizes, int n_in,
                              void* d_out, int out_size) {
    const float* k  = (const float*)d_in[0];
    const float* v  = (const float*)d_in[1];
    const float* r  = (const float*)d_in[2];
    const float* s0 = (const float*)d_in[3];
    const float* tf = (const float*)d_in[4];
    const float* td = (const float*)d_in[5];
    float* out = (float*)d_out;

    int warps = T_DIM * H_DIM;
    int blocks = (warps * 32) / 256;
    rtfk_kernel<<<blocks, 256>>>(k, r, tf);

    dim3 grid(N_DIM / JB, H_DIM);   // (4, 32) = 128 blocks
    wkv_kernel<<<grid, THREADS>>>(k, v, r, s0, td, out, out_size);
}

// round 3
// speedup vs baseline: 3.1595x; 2.7322x over previous
#include <cuda_runtime.h>

#define TD 8192
#define HD 32
#define ND 64
#define LC 32              // chunk length
#define NC (TD / LC)       // 256 chunks
#define HN (HD * ND)       // 2048
#define HNN (HD * ND * ND) // 131072

typedef unsigned long long ull;

__device__ __forceinline__ ull pk2(float x, float y) {
    ull r; asm("mov.b64 %0, {%1,%2};" : "=l"(r) : "f"(x), "f"(y)); return r;
}
__device__ __forceinline__ void upk2(float& x, float& y, ull a) {
    asm("mov.b64 {%0,%1}, %2;" : "=f"(x), "=f"(y) : "l"(a));
}
__device__ __forceinline__ ull fma2(ull a, ull b, ull c) {
    ull d; asm("fma.rn.f32x2 %0, %1, %2, %3;" : "=l"(d) : "l"(a), "l"(b), "l"(c)); return d;
}

// scratch (module-scope device globals; no runtime allocation)
__device__ float gA[NC * HNN];       // chunk transition matrices   (134 MB)
__device__ float gD[NC * HD * ND];   // chunk decay products        (2 MB)
__device__ float gS[NC * HNN];       // inbound state per chunk     (134 MB)

// ---------------- K1: per-chunk transition (A_c, D_c) ----------------
// grid (NC, HD), 128 threads
__global__ __launch_bounds__(128)
void chunk_kernel(const float* __restrict__ k, const float* __restrict__ v,
                  const float* __restrict__ td) {
    __shared__ float sk[LC][ND], sv[LC][ND], sw[LC][ND], skq[LC][ND];
    const int tid = threadIdx.x, c = blockIdx.x, h = blockIdx.y;
    const int t0 = c * LC;

#pragma unroll
    for (int p = 0; p < 4; ++p) {
        int f = tid + 128 * p;                 // float4 index (512 total)
        int t = f >> 4, c4 = (f & 15) << 2;
        size_t g = ((size_t)(t0 + t) * HD + h) * ND + c4;
        *(float4*)&sk[t][c4] = *(const float4*)(k + g);
        *(float4*)&sv[t][c4] = *(const float4*)(v + g);
        *(float4*)&sw[t][c4] = *(const float4*)(td + g);
    }
    __syncthreads();

    if (tid < ND) {
        const int i = tid;
        float Q = 1.f;
#pragma unroll 8
        for (int t = LC - 1; t >= 0; --t) {
            skq[t][i] = Q * sk[t][i];          // suffix product * k  (all <= O(1))
            Q *= sw[t][i];
        }
        gD[(c * HD + h) * ND + i] = Q;         // full chunk decay
    }
    __syncthreads();

    const int i0 = (tid >> 3) * 4, j0 = (tid & 7) * 8;
    ull acc[4][4];
#pragma unroll
    for (int a = 0; a < 4; ++a)
#pragma unroll
        for (int b = 0; b < 4; ++b) acc[a][b] = 0ULL;

#pragma unroll 4
    for (int t = 0; t < LC; ++t) {
        float4 kq = *(const float4*)&skq[t][i0];
        float4 va = *(const float4*)&sv[t][j0];
        float4 vb = *(const float4*)&sv[t][j0 + 4];
        ull v0 = pk2(va.x, va.y), v1 = pk2(va.z, va.w);
        ull v2 = pk2(vb.x, vb.y), v3 = pk2(vb.z, vb.w);
        ull q0 = pk2(kq.x, kq.x), q1 = pk2(kq.y, kq.y);
        ull q2 = pk2(kq.z, kq.z), q3 = pk2(kq.w, kq.w);
        acc[0][0]=fma2(q0,v0,acc[0][0]); acc[0][1]=fma2(q0,v1,acc[0][1]);
        acc[0][2]=fma2(q0,v2,acc[0][2]); acc[0][3]=fma2(q0,v3,acc[0][3]);
        acc[1][0]=fma2(q1,v0,acc[1][0]); acc[1][1]=fma2(q1,v1,acc[1][1]);
        acc[1][2]=fma2(q1,v2,acc[1][2]); acc[1][3]=fma2(q1,v3,acc[1][3]);
        acc[2][0]=fma2(q2,v0,acc[2][0]); acc[2][1]=fma2(q2,v1,acc[2][1]);
        acc[2][2]=fma2(q2,v2,acc[2][2]); acc[2][3]=fma2(q2,v3,acc[2][3]);
        acc[3][0]=fma2(q3,v0,acc[3][0]); acc[3][1]=fma2(q3,v1,acc[3][1]);
        acc[3][2]=fma2(q3,v2,acc[3][2]); acc[3][3]=fma2(q3,v3,acc[3][3]);
    }
    float* op = gA + ((size_t)(c * HD + h) * ND + i0) * ND + j0;
#pragma unroll
    for (int a = 0; a < 4; ++a) {
        float4 o1, o2;
        upk2(o1.x, o1.y, acc[a][0]); upk2(o1.z, o1.w, acc[a][1]);
        upk2(o2.x, o2.y, acc[a][2]); upk2(o2.z, o2.w, acc[a][3]);
        *(float4*)(op + a * ND)     = o1;
        *(float4*)(op + a * ND + 4) = o2;
    }
}

// ---------------- K2: inter-chunk scan ----------------
// grid 128 (= HD * 4 j-slices), 256 threads; element-parallel, 8-deep LDG ring
#define DEP 8
__global__ __launch_bounds__(256)
void scan_kernel(const float* __restrict__ s0, float* __restrict__ out) {
    const int tid = threadIdx.x;
    const int h = blockIdx.x >> 2, js = blockIdx.x & 3;
    const int i = tid >> 2, j = js * 16 + (tid & 3) * 4;
    const size_t eoff = (size_t)(h * ND + i) * ND + j;
    const int doff = h * ND + i;

    float4 cur = *(const float4*)(s0 + eoff);
    float4 bA[DEP]; float bD[DEP];
#pragma unroll
    for (int d = 0; d < DEP; ++d) {
        bA[d] = *(const float4*)(gA + (size_t)d * HNN + eoff);
        bD[d] = gD[d * HN + doff];
    }
    for (int cb = 0; cb < NC; cb += DEP) {
#pragma unroll
        for (int d = 0; d < DEP; ++d) {
            int c = cb + d;
            *(float4*)(gS + (size_t)c * HNN + eoff) = cur;   // inbound state
            float4 a = bA[d]; float dd = bD[d];
            int cn = c + DEP;
            if (cn < NC) {
                bA[d] = *(const float4*)(gA + (size_t)cn * HNN + eoff);
                bD[d] = gD[cn * HN + doff];
            }
            cur.x = fmaf(dd, cur.x, a.x);
            cur.y = fmaf(dd, cur.y, a.y);
            cur.z = fmaf(dd, cur.z, a.z);
            cur.w = fmaf(dd, cur.w, a.w);
        }
    }
    *(float4*)(out + (size_t)TD * HN + eoff) = cur;          // final state
}

// ---------------- K3: per-chunk outputs ----------------
// grid (NC, HD), 128 threads
__global__ __launch_bounds__(128)
void out_kernel(const float* __restrict__ k, const float* __restrict__ v,
                const float* __restrict__ r, const float* __restrict__ td,
                const float* __restrict__ tf, float* __restrict__ out) {
    __shared__ float sS[ND][ND];          // inbound state [i][j]
    __shared__ float svs[LC][ND];         // v chunk [t][j]
    __shared__ float sQt[ND][LC + 1];     // (r*P)^T  [i][t], pad 33
    __shared__ float sKk[ND][LC + 1];     // (k/P)^T  [i][t'], pad 33
    __shared__ float sAt[LC][LC + 1];     // att^T    [t'][t], pad 33
    __shared__ float sBp[LC][2];          // bonus partials

    const int tid = threadIdx.x, c = blockIdx.x, h = blockIdx.y;
    const int t0 = c * LC;

    {
        const float* gSin = gS + (size_t)c * HNN + (size_t)h * ND * ND;
#pragma unroll
        for (int p = 0; p < 8; ++p) {
            int f = tid + 128 * p;
            int i = f >> 4, c4 = (f & 15) << 2;
            *(float4*)&sS[i][c4] = *(const float4*)(gSin + i * ND + c4);
        }
#pragma unroll
        for (int p = 0; p < 4; ++p) {
            int f = tid + 128 * p;
            int t = f >> 4, c4 = (f & 15) << 2;
            *(float4*)&svs[t][c4] =
                *(const float4*)(v + ((size_t)(t0 + t) * HD + h) * ND + c4);
        }
    }

    if (tid < ND) {
        const int i = tid;
        const float* rp = r  + (size_t)t0 * HN + h * ND + i;
        const float* kp = k  + (size_t)t0 * HN + h * ND + i;
        const float* wp = td + (size_t)t0 * HN + h * ND + i;
        float P = 1.f;
#pragma unroll 8
        for (int t = 0; t < LC; ++t) {
            sQt[i][t] = rp[(size_t)t * HN] * P;
            float wv = fmaxf(wp[(size_t)t * HN], 1e-6f);   // guard exact zeros
            P *= wv;
            sKk[i][t] = __fdividef(kp[(size_t)t * HN], P);
        }
    } else {
        const int q = tid - 64, t = q >> 1, half = q & 1;
        const float* rp = r  + (size_t)(t0 + t) * HN + h * ND + half * 32;
        const float* kp = k  + (size_t)(t0 + t) * HN + h * ND + half * 32;
        const float* fp = tf + h * ND + half * 32;
        float s = 0.f;
#pragma unroll
        for (int x = 0; x < 8; ++x) {
            float4 r4 = *(const float4*)(rp + 4 * x);
            float4 k4 = *(const float4*)(kp + 4 * x);
            float4 f4 = *(const float4*)(fp + 4 * x);
            s += r4.x * k4.x * f4.x + r4.y * k4.y * f4.y
               + r4.z * k4.z * f4.z + r4.w * k4.w * f4.w;
        }
        sBp[t][half] = s;
    }
    __syncthreads();

    // att[t][t'] = sum_i qt[t][i]*kk[t'][i]; thread = (tg: 2 t) x (pg: 4 t')
    {
        const int ta = (tid >> 3) * 2, pb = (tid & 7) * 4;
        ull a0 = 0, a1 = 0, a2 = 0, a3 = 0;
#pragma unroll 8
        for (int i = 0; i < ND; ++i) {
            float q0 = sQt[i][ta], q1 = sQt[i][ta + 1];
            float x0 = sKk[i][pb],     x1 = sKk[i][pb + 1];
            float x2 = sKk[i][pb + 2], x3 = sKk[i][pb + 3];
            ull kk01 = pk2(x0, x1), kk23 = pk2(x2, x3);
            ull q0d = pk2(q0, q0), q1d = pk2(q1, q1);
            a0 = fma2(q0d, kk01, a0); a1 = fma2(q0d, kk23, a1);
            a2 = fma2(q1d, kk01, a2); a3 = fma2(q1d, kk23, a3);
        }
        float e[2][4];
        upk2(e[0][0], e[0][1], a0); upk2(e[0][2], e[0][3], a1);
        upk2(e[1][0], e[1][1], a2); upk2(e[1][2], e[1][3], a3);
#pragma unroll
        for (int x = 0; x < 2; ++x) {
            int t = ta + x;
            float bt = sBp[t][0] + sBp[t][1];
#pragma unroll
            for (int y = 0; y < 4; ++y) {
                int tp = pb + y;
                sAt[tp][t] = tp < t ? e[x][y] : (tp == t ? bt : 0.f);
            }
        }
    }
    __syncthreads();

    // out = att@V + Qt@S ; thread = (tg: 4 t) x (jg: 4 j)
    {
        const int tb = (tid >> 4) * 4, j0 = (tid & 15) * 4;
        ull acc[4][2];
#pragma unroll
        for (int a = 0; a < 4; ++a) { acc[a][0] = 0ULL; acc[a][1] = 0ULL; }

#pragma unroll 8
        for (int i = 0; i < ND; ++i) {
            float q0 = sQt[i][tb],     q1 = sQt[i][tb + 1];
            float q2 = sQt[i][tb + 2], q3 = sQt[i][tb + 3];
            float4 s4 = *(const float4*)&sS[i][j0];
            ull sA = pk2(s4.x, s4.y), sB = pk2(s4.z, s4.w);
            acc[0][0] = fma2(pk2(q0, q0), sA, acc[0][0]);
            acc[0][1] = fma2(pk2(q0, q0), sB, acc[0][1]);
            acc[1][0] = fma2(pk2(q1, q1), sA, acc[1][0]);
            acc[1][1] = fma2(pk2(q1, q1), sB, acc[1][1]);
            acc[2][0] = fma2(pk2(q2, q2), sA, acc[2][0]);
            acc[2][1] = fma2(pk2(q2, q2), sB, acc[2][1]);
            acc[3][0] = fma2(pk2(q3, q3), sA, acc[3][0]);
            acc[3][1] = fma2(pk2(q3, q3), sB, acc[3][1]);
        }
#pragma unroll 8
        for (int tp = 0; tp < LC; ++tp) {
            float w0 = sAt[tp][tb],     w1 = sAt[tp][tb + 1];
            float w2 = sAt[tp][tb + 2], w3 = sAt[tp][tb + 3];
            float4 v4 = *(const float4*)&svs[tp][j0];
            ull vA = pk2(v4.x, v4.y), vB = pk2(v4.z, v4.w);
            acc[0][0] = fma2(pk2(w0, w0), vA, acc[0][0]);
            acc[0][1] = fma2(pk2(w0, w0), vB, acc[0][1]);
            acc[1][0] = fma2(pk2(w1, w1), vA, acc[1][0]);
            acc[1][1] = fma2(pk2(w1, w1), vB, acc[1][1]);
            acc[2][0] = fma2(pk2(w2, w2), vA, acc[2][0]);
            acc[2][1] = fma2(pk2(w2, w2), vB, acc[2][1]);
            acc[3][0] = fma2(pk2(w3, w3), vA, acc[3][0]);
            acc[3][1] = fma2(pk2(w3, w3), vB, acc[3][1]);
        }
#pragma unroll
        for (int x = 0; x < 4; ++x) {
            float4 o;
            upk2(o.x, o.y, acc[x][0]); upk2(o.z, o.w, acc[x][1]);
            *(float4*)(out + ((size_t)(t0 + tb + x) * HD + h) * ND + j0) = o;
        }
    }
}

extern "C" void kernel_launch(void* const* d_in, const int* in_sizes, int n_in,
                              void* d_out, int out_size) {
    const float* k  = (const float*)d_in[0];
    const float* v  = (const float*)d_in[1];
    const float* r  = (const float*)d_in[2];
    const float* s0 = (const float*)d_in[3];
    const float* tf = (const float*)d_in[4];
    const float* td = (const float*)d_in[5];
    float* out = (float*)d_out;

    dim3 gc(NC, HD);
    chunk_kernel<<<gc, 128>>>(k, v, td);
    scan_kernel<<<HD * 4, 256>>>(s0, out);
    out_kernel<<<gc, 128>>>(k, v, r, td, tf, out);
}